// round 13
// baseline (speedup 1.0000x reference)
#include <cuda_runtime.h>
#include <cstdint>

#define BLOCK 512
#define NBLK  4                   // CTAs per SM (2048 threads/SM)
#define GRID  (148 * NBLK)        // 592
#define TILE_F4 (BLOCK * 2)       // 1024 float4 per tile per array (16KB/array)
#define MAX_TILES 16384           // covers n4 up to 16.7M (N=67M); ours: 8192 tiles

__device__ float g_tile_sums[MAX_TILES];
__device__ float g_partials[GRID];     // static remainder path (empty for our N)
__device__ unsigned int g_work;        // tile scheduler; last block resets
__device__ unsigned int g_count;       // arrival counter; last block resets

__device__ __forceinline__ float dz2(float a, float b) {
    float d = a - b;
    d = (fabsf(d) < 0.1f) ? 0.0f : d;
    return d * d;
}

__global__ __launch_bounds__(BLOCK, NBLK) void deadzone_loss_kernel(
    const float* __restrict__ inputs,
    const float* __restrict__ targets,
    float* __restrict__ out,
    int n, float inv_n)
{
    const float4* __restrict__ in4 = reinterpret_cast<const float4*>(inputs);
    const float4* __restrict__ tg4 = reinterpret_cast<const float4*>(targets);

    int n4 = n >> 2;
    int tiles = n4 / TILE_F4;
    if (tiles > MAX_TILES) tiles = MAX_TILES;

    int lane = threadIdx.x & 31;
    int wid  = threadIdx.x >> 5;

    __shared__ float warp_sums[BLOCK / 32];
    __shared__ unsigned int s_t;
    __shared__ bool is_last;

    // ---- dynamic tile loop (work-stealing; deterministic per-tile sums) ----
    if (threadIdx.x == 0) s_t = atomicAdd(&g_work, 1u);
    __syncthreads();
    unsigned int t = s_t;

    while (t < (unsigned)tiles) {
        int base = (int)t * TILE_F4 + threadIdx.x;
        float4 a0 = in4[base];
        float4 b0 = tg4[base];
        float4 a1 = in4[base + BLOCK];
        float4 b1 = tg4[base + BLOCK];

        float acc = dz2(a0.x, b0.x) + dz2(a0.y, b0.y)
                  + dz2(a0.z, b0.z) + dz2(a0.w, b0.w)
                  + dz2(a1.x, b1.x) + dz2(a1.y, b1.y)
                  + dz2(a1.z, b1.z) + dz2(a1.w, b1.w);

        #pragma unroll
        for (int off = 16; off > 0; off >>= 1)
            acc += __shfl_down_sync(0xFFFFFFFFu, acc, off);
        if (lane == 0) warp_sums[wid] = acc;
        if (threadIdx.x == 0) s_t = atomicAdd(&g_work, 1u);   // prefetch next tile
        __syncthreads();

        if (wid == 0) {
            float v = (lane < BLOCK / 32) ? warp_sums[lane] : 0.0f;
            #pragma unroll
            for (int off = 8; off > 0; off >>= 1)
                v += __shfl_down_sync(0xFFFFFFFFu, v, off);
            if (lane == 0) g_tile_sums[t] = v;   // fixed slot -> deterministic
        }
        t = s_t;
        __syncthreads();   // protect warp_sums before next iteration overwrites
    }

    // ---- static remainder: float4 beyond tiles*TILE_F4, plus scalar tail ----
    {
        float racc = 0.0f;
        int tid = blockIdx.x * BLOCK + threadIdx.x;
        const int stride = GRID * BLOCK;
        for (int i = tiles * TILE_F4 + tid; i < n4; i += stride) {
            float4 a = in4[i];
            float4 b = tg4[i];
            racc += dz2(a.x, b.x) + dz2(a.y, b.y) + dz2(a.z, b.z) + dz2(a.w, b.w);
        }
        for (int j = (n4 << 2) + tid; j < n; j += stride)
            racc += dz2(inputs[j], targets[j]);

        #pragma unroll
        for (int off = 16; off > 0; off >>= 1)
            racc += __shfl_down_sync(0xFFFFFFFFu, racc, off);
        if (lane == 0) warp_sums[wid] = racc;
        __syncthreads();
        if (wid == 0) {
            float v = (lane < BLOCK / 32) ? warp_sums[lane] : 0.0f;
            #pragma unroll
            for (int off = 8; off > 0; off >>= 1)
                v += __shfl_down_sync(0xFFFFFFFFu, v, off);
            if (lane == 0) {
                g_partials[blockIdx.x] = v;
                __threadfence();
                unsigned int done = atomicAdd(&g_count, 1u);
                is_last = (done == GRID - 1);
            }
        }
    }
    __syncthreads();

    // ---- last block: fixed-order final reduction (bitwise deterministic) ----
    if (is_last) {
        float v = 0.0f;
        for (int k = threadIdx.x; k < tiles; k += BLOCK)
            v += g_tile_sums[k];
        for (int k = threadIdx.x; k < GRID; k += BLOCK)
            v += g_partials[k];

        #pragma unroll
        for (int off = 16; off > 0; off >>= 1)
            v += __shfl_down_sync(0xFFFFFFFFu, v, off);
        if (lane == 0) warp_sums[wid] = v;
        __syncthreads();

        if (wid == 0) {
            float s = (lane < BLOCK / 32) ? warp_sums[lane] : 0.0f;
            #pragma unroll
            for (int off = 8; off > 0; off >>= 1)
                s += __shfl_down_sync(0xFFFFFFFFu, s, off);
            if (lane == 0) {
                out[0] = s * inv_n;
                g_work = 0;    // reset scheduler for next graph replay
                g_count = 0;
            }
        }
    }
}

extern "C" void kernel_launch(void* const* d_in, const int* in_sizes, int n_in,
                              void* d_out, int out_size)
{
    const float* inputs  = (const float*)d_in[0];
    const float* targets = (const float*)d_in[1];
    float* out = (float*)d_out;
    int n = in_sizes[0];

    deadzone_loss_kernel<<<GRID, BLOCK>>>(inputs, targets, out, n, 1.0f / (float)n);
}

// round 14
// speedup vs baseline: 1.0934x; 1.0934x over previous
#include <cuda_runtime.h>
#include <cstdint>

#define BLOCK 512
#define NBLK  4                 // CTAs per SM (2048 threads/SM)
#define GRID  (148 * NBLK)      // 592: exactly one wave

__device__ float g_partials[GRID];
__device__ unsigned int g_count;   // zero-init; last block resets -> graph-replay safe

__global__ __launch_bounds__(BLOCK, NBLK) void deadzone_loss_kernel(
    const float* __restrict__ inputs,
    const float* __restrict__ targets,
    float* __restrict__ out,
    int n, float inv_n)
{
    const float ERROR_OK = 0.1f;
    float acc0 = 0.0f, acc1 = 0.0f;

    int n4 = n >> 2;
    const float4* __restrict__ in4 = reinterpret_cast<const float4*>(inputs);
    const float4* __restrict__ tg4 = reinterpret_cast<const float4*>(targets);

    int tid = blockIdx.x * BLOCK + threadIdx.x;
    const int stride = GRID * BLOCK;   // compile-time -> immediate LDG offsets

    int i = tid;
    // converged mainloop: 4 independent LDG.128 per iteration, chip-wide
    // grid-stride (optimal for the B300 addr->LTS hash), full occupancy
    for (; i + stride < n4; i += 2 * stride) {
        float4 a0 = in4[i];
        float4 b0 = tg4[i];
        float4 a1 = in4[i + stride];
        float4 b1 = tg4[i + stride];

        float d;
        d = a0.x - b0.x; d = (fabsf(d) < ERROR_OK) ? 0.0f : d; acc0 = fmaf(d, d, acc0);
        d = a0.y - b0.y; d = (fabsf(d) < ERROR_OK) ? 0.0f : d; acc1 = fmaf(d, d, acc1);
        d = a0.z - b0.z; d = (fabsf(d) < ERROR_OK) ? 0.0f : d; acc0 = fmaf(d, d, acc0);
        d = a0.w - b0.w; d = (fabsf(d) < ERROR_OK) ? 0.0f : d; acc1 = fmaf(d, d, acc1);
        d = a1.x - b1.x; d = (fabsf(d) < ERROR_OK) ? 0.0f : d; acc0 = fmaf(d, d, acc0);
        d = a1.y - b1.y; d = (fabsf(d) < ERROR_OK) ? 0.0f : d; acc1 = fmaf(d, d, acc1);
        d = a1.z - b1.z; d = (fabsf(d) < ERROR_OK) ? 0.0f : d; acc0 = fmaf(d, d, acc0);
        d = a1.w - b1.w; d = (fabsf(d) < ERROR_OK) ? 0.0f : d; acc1 = fmaf(d, d, acc1);
    }
    for (; i < n4; i += stride) {
        float4 a = in4[i];
        float4 b = tg4[i];
        float d;
        d = a.x - b.x; d = (fabsf(d) < ERROR_OK) ? 0.0f : d; acc0 = fmaf(d, d, acc0);
        d = a.y - b.y; d = (fabsf(d) < ERROR_OK) ? 0.0f : d; acc1 = fmaf(d, d, acc1);
        d = a.z - b.z; d = (fabsf(d) < ERROR_OK) ? 0.0f : d; acc0 = fmaf(d, d, acc0);
        d = a.w - b.w; d = (fabsf(d) < ERROR_OK) ? 0.0f : d; acc1 = fmaf(d, d, acc1);
    }
    // scalar tail (N is a multiple of 4, but stay general)
    for (int j = (n4 << 2) + tid; j < n; j += stride) {
        float d = inputs[j] - targets[j];
        d = (fabsf(d) < ERROR_OK) ? 0.0f : d;
        acc0 = fmaf(d, d, acc0);
    }

    float acc = acc0 + acc1;

    // warp reduction
    #pragma unroll
    for (int off = 16; off > 0; off >>= 1)
        acc += __shfl_down_sync(0xFFFFFFFFu, acc, off);

    __shared__ float warp_sums[BLOCK / 32];
    int lane = threadIdx.x & 31;
    int wid  = threadIdx.x >> 5;
    if (lane == 0) warp_sums[wid] = acc;
    __syncthreads();

    __shared__ bool is_last;
    if (wid == 0) {
        float v = (lane < BLOCK / 32) ? warp_sums[lane] : 0.0f;
        #pragma unroll
        for (int off = 16; off > 0; off >>= 1)
            v += __shfl_down_sync(0xFFFFFFFFu, v, off);
        if (lane == 0) {
            g_partials[blockIdx.x] = v;
            __threadfence();
            unsigned int done = atomicAdd(&g_count, 1u);
            is_last = (done == GRID - 1);
        }
    }
    __syncthreads();

    // last block reduces all partials (deterministic order)
    if (is_last) {
        float v = 0.0f;
        for (int k = threadIdx.x; k < GRID; k += BLOCK)
            v += g_partials[k];

        #pragma unroll
        for (int off = 16; off > 0; off >>= 1)
            v += __shfl_down_sync(0xFFFFFFFFu, v, off);

        if (lane == 0) warp_sums[wid] = v;
        __syncthreads();

        if (wid == 0) {
            float s = (lane < BLOCK / 32) ? warp_sums[lane] : 0.0f;
            #pragma unroll
            for (int off = 16; off > 0; off >>= 1)
                s += __shfl_down_sync(0xFFFFFFFFu, s, off);
            if (lane == 0) {
                out[0] = s * inv_n;
                g_count = 0;   // reset for next graph replay
            }
        }
    }
}

extern "C" void kernel_launch(void* const* d_in, const int* in_sizes, int n_in,
                              void* d_out, int out_size)
{
    const float* inputs  = (const float*)d_in[0];
    const float* targets = (const float*)d_in[1];
    float* out = (float*)d_out;
    int n = in_sizes[0];

    deadzone_loss_kernel<<<GRID, BLOCK>>>(inputs, targets, out, n, 1.0f / (float)n);
}